// round 1
// baseline (speedup 1.0000x reference)
#include <cuda_runtime.h>
#include <cuda_bf16.h>
#include <cstdint>

// Problem constants (fixed by the dataset)
#define NU 100000          // users
#define NM 20000           // movies
#define NE 1000000         // edges per direction
#define NLOOP 20000        // min(NU,NM) self loops (PyG add_self_loops on bipartite)
#define ET (NE + NLOOP)    // total edges per conv
#define HD 64              // hidden dim

// ---------------- scratch (static device globals; no runtime allocation) ----
__device__ float g_xl[(size_t)NU * HD];      // src projection (max size)
__device__ float g_xr[(size_t)NU * HD];      // dst projection (max size)
__device__ float g_score[ET];
__device__ float g_ex[ET];
__device__ int   g_m[NU];                    // encoded segment max
__device__ float g_s[NU];                    // segment sum of exp
__device__ float g_accu[(size_t)NU * HD];    // user-dst accumulator
__device__ float g_accm[(size_t)NM * HD];    // movie-dst accumulator
__device__ float g_xu[(size_t)NU * HD];      // layer-0 user output
__device__ float g_xm[(size_t)NM * HD];      // layer-0 movie output

// ---------------- GEMM: Y[N,64] = X[N,64] @ W[64,64] + B[64] ----------------
__global__ void gemm_bias_k(const float* __restrict__ X, const float* __restrict__ W,
                            const float* __restrict__ B, float* __restrict__ Y, int N)
{
    __shared__ float Xs[64][65];
    __shared__ float Ws[64][64];
    int tid  = threadIdx.x;              // 256 threads
    int row0 = blockIdx.x * 64;

    const float4* W4 = (const float4*)W;
    float4* Ws4 = (float4*)Ws;
#pragma unroll
    for (int i = 0; i < 4; i++) Ws4[tid + i * 256] = W4[tid + i * 256];

#pragma unroll
    for (int i = 0; i < 4; i++) {
        int idx = tid + i * 256;         // float4 index over [64][16]
        int r = idx >> 4, c4 = idx & 15;
        float4 v = make_float4(0.f, 0.f, 0.f, 0.f);
        if (row0 + r < N) v = ((const float4*)X)[(size_t)(row0 + r) * 16 + c4];
        Xs[r][c4 * 4 + 0] = v.x; Xs[r][c4 * 4 + 1] = v.y;
        Xs[r][c4 * 4 + 2] = v.z; Xs[r][c4 * 4 + 3] = v.w;
    }
    __syncthreads();

    int ty = tid >> 4, tx = tid & 15;    // 4 rows x 4 cols per thread
    float acc[4][4];
#pragma unroll
    for (int i = 0; i < 4; i++)
#pragma unroll
        for (int j = 0; j < 4; j++) acc[i][j] = 0.f;

#pragma unroll
    for (int k = 0; k < 64; k++) {
        float4 wv = ((const float4*)Ws)[k * 16 + tx];
        float x0 = Xs[ty * 4 + 0][k];
        float x1 = Xs[ty * 4 + 1][k];
        float x2 = Xs[ty * 4 + 2][k];
        float x3 = Xs[ty * 4 + 3][k];
        acc[0][0] += x0 * wv.x; acc[0][1] += x0 * wv.y; acc[0][2] += x0 * wv.z; acc[0][3] += x0 * wv.w;
        acc[1][0] += x1 * wv.x; acc[1][1] += x1 * wv.y; acc[1][2] += x1 * wv.z; acc[1][3] += x1 * wv.w;
        acc[2][0] += x2 * wv.x; acc[2][1] += x2 * wv.y; acc[2][2] += x2 * wv.z; acc[2][3] += x2 * wv.w;
        acc[3][0] += x3 * wv.x; acc[3][1] += x3 * wv.y; acc[3][2] += x3 * wv.z; acc[3][3] += x3 * wv.w;
    }

    float4 bv = ((const float4*)B)[tx];
#pragma unroll
    for (int i = 0; i < 4; i++) {
        int r = row0 + ty * 4 + i;
        if (r < N) {
            float4 o;
            o.x = acc[i][0] + bv.x; o.y = acc[i][1] + bv.y;
            o.z = acc[i][2] + bv.z; o.w = acc[i][3] + bv.w;
            ((float4*)Y)[(size_t)r * 16 + tx] = o;
        }
    }
}

// ---------------- per-conv init --------------------------------------------
__global__ void init_k(int* __restrict__ mbuf, float* __restrict__ sbuf,
                       float* __restrict__ acc, int ndst)
{
    int i = blockIdx.x * blockDim.x + threadIdx.x;
    int n = ndst * HD;
    if (i < n) acc[i] = 0.f;
    if (i < ndst) { mbuf[i] = (int)0x807FFFFFu; sbuf[i] = 0.f; }  // enc(-inf)
}

// ---------------- edge pass 1: score + segment max --------------------------
__global__ void edge_score_k(const int* __restrict__ esrc, const int* __restrict__ edst,
                             const float* __restrict__ xl, const float* __restrict__ xr,
                             const float* __restrict__ att,
                             float* __restrict__ score, int* __restrict__ mbuf)
{
    int t = blockIdx.x * blockDim.x + threadIdx.x;
    int g = t >> 4;
    if (g >= ET) return;
    int lane = t & 15;
    int s, d;
    if (g < NE) { s = esrc[g]; d = edst[g]; } else { s = g - NE; d = s; }

    float4 a = ((const float4*)xl)[(size_t)s * 16 + lane];
    float4 b = ((const float4*)xr)[(size_t)d * 16 + lane];
    float4 w = ((const float4*)att)[lane];

    float vx = a.x + b.x; vx = vx > 0.f ? vx : 0.2f * vx;
    float vy = a.y + b.y; vy = vy > 0.f ? vy : 0.2f * vy;
    float vz = a.z + b.z; vz = vz > 0.f ? vz : 0.2f * vz;
    float vw = a.w + b.w; vw = vw > 0.f ? vw : 0.2f * vw;
    float p = vx * w.x + vy * w.y + vz * w.z + vw * w.w;
#pragma unroll
    for (int o = 8; o > 0; o >>= 1) p += __shfl_xor_sync(0xffffffffu, p, o);

    if (lane == 0) {
        score[g] = p;
        int e = __float_as_int(p);
        if (e < 0) e ^= 0x7FFFFFFF;     // order-preserving float->int
        atomicMax(&mbuf[d], e);
    }
}

// ---------------- edge pass 2: exp + segment sum ----------------------------
__global__ void edge_exp_k(const int* __restrict__ edst, const float* __restrict__ score,
                           const int* __restrict__ mbuf,
                           float* __restrict__ ex, float* __restrict__ sbuf)
{
    int g = blockIdx.x * blockDim.x + threadIdx.x;
    if (g >= ET) return;
    int d = (g < NE) ? edst[g] : g - NE;
    int k = mbuf[d];
    float m = (k >= 0) ? __int_as_float(k) : __int_as_float(k ^ 0x7FFFFFFF);
    float e = __expf(score[g] - m);
    ex[g] = e;
    atomicAdd(&sbuf[d], e);
}

// ---------------- edge pass 3: weighted scatter -----------------------------
__global__ void edge_scatter_k(const int* __restrict__ esrc, const int* __restrict__ edst,
                               const float* __restrict__ xl, const float* __restrict__ ex,
                               const float* __restrict__ sbuf, float* __restrict__ acc)
{
    int t = blockIdx.x * blockDim.x + threadIdx.x;
    int g = t >> 4;
    if (g >= ET) return;
    int lane = t & 15;
    int s, d;
    if (g < NE) { s = esrc[g]; d = edst[g]; } else { s = g - NE; d = s; }

    float alpha = ex[g] / (sbuf[d] + 1e-16f);        // broadcast loads (L1 hit)
    float4 a = ((const float4*)xl)[(size_t)s * 16 + lane];
    a.x *= alpha; a.y *= alpha; a.z *= alpha; a.w *= alpha;
    float* p = acc + (size_t)d * HD + lane * 4;
    asm volatile("red.global.add.v4.f32 [%0], {%1,%2,%3,%4};"
                 :: "l"(p), "f"(a.x), "f"(a.y), "f"(a.z), "f"(a.w) : "memory");
}

// ---------------- finalize: + bias, SELU ------------------------------------
__global__ void finalize_k(const float* __restrict__ acc, const float* __restrict__ bias,
                           float* __restrict__ out, int n)
{
    int i = blockIdx.x * blockDim.x + threadIdx.x;
    if (i >= n) return;
    float x = acc[i] + bias[i & 63];
    const float SCALE = 1.0507009873554805f;
    const float SA    = 1.7580993408473766f;   // scale * alpha
    out[i] = x > 0.f ? SCALE * x : SA * (__expf(x) - 1.f);
}

// ---------------- host-side conv driver -------------------------------------
static void launch_conv(const float* xs, int ns, const float* xd, int nd,
                        const int* edge,
                        const float* Wl_, const float* bl_,
                        const float* Wr_, const float* br_, const float* att_,
                        float* xl, float* xr, float* sc, float* ex,
                        int* mm, float* sb, float* acc)
{
    gemm_bias_k<<<(ns + 63) / 64, 256>>>(xs, Wl_, bl_, xl, ns);
    gemm_bias_k<<<(nd + 63) / 64, 256>>>(xd, Wr_, br_, xr, nd);
    init_k<<<(nd * HD + 255) / 256, 256>>>(mm, sb, acc, nd);
    edge_score_k<<<((long)ET * 16 + 255) / 256, 256>>>(edge, edge + NE, xl, xr, att_, sc, mm);
    edge_exp_k<<<(ET + 255) / 256, 256>>>(edge + NE, sc, mm, ex, sb);
    edge_scatter_k<<<((long)ET * 16 + 255) / 256, 256>>>(edge, edge + NE, xl, ex, sb, acc);
}

extern "C" void kernel_launch(void* const* d_in, const int* in_sizes, int n_in,
                              void* d_out, int out_size)
{
    const float* x_user  = (const float*)d_in[0];
    const float* x_movie = (const float*)d_in[1];
    const int*   e_u2m   = (const int*)d_in[2];
    const int*   e_m2u   = (const int*)d_in[3];
    const float* Wl      = (const float*)d_in[4];
    const float* bl      = (const float*)d_in[5];
    const float* Wr      = (const float*)d_in[6];
    const float* br      = (const float*)d_in[7];
    const float* att     = (const float*)d_in[8];
    const float* bias    = (const float*)d_in[9];
    float* out = (float*)d_out;

    float *xl, *xr, *sc, *ex, *sb, *accu, *accm, *xu, *xm;
    int *mm;
    cudaGetSymbolAddress((void**)&xl,   g_xl);
    cudaGetSymbolAddress((void**)&xr,   g_xr);
    cudaGetSymbolAddress((void**)&sc,   g_score);
    cudaGetSymbolAddress((void**)&ex,   g_ex);
    cudaGetSymbolAddress((void**)&mm,   g_m);
    cudaGetSymbolAddress((void**)&sb,   g_s);
    cudaGetSymbolAddress((void**)&accu, g_accu);
    cudaGetSymbolAddress((void**)&accm, g_accm);
    cudaGetSymbolAddress((void**)&xu,   g_xu);
    cudaGetSymbolAddress((void**)&xm,   g_xm);

    const float* cu = x_user;
    const float* cm = x_movie;

    for (int l = 0; l < 2; l++) {
        int p0 = l * 2 + 0;   // user -> movie
        int p1 = l * 2 + 1;   // movie -> user

        // conv u2m: src=user, dst=movie  -> accm
        launch_conv(cu, NU, cm, NM, e_u2m,
                    Wl + (size_t)p0 * 4096, bl + (size_t)p0 * 64,
                    Wr + (size_t)p0 * 4096, br + (size_t)p0 * 64,
                    att + (size_t)p0 * 64,
                    xl, xr, sc, ex, mm, sb, accm);

        // conv m2u: src=movie, dst=user  -> accu (reads OLD features)
        launch_conv(cm, NM, cu, NU, e_m2u,
                    Wl + (size_t)p1 * 4096, bl + (size_t)p1 * 64,
                    Wr + (size_t)p1 * 4096, br + (size_t)p1 * 64,
                    att + (size_t)p1 * 64,
                    xl, xr, sc, ex, mm, sb, accu);

        float* movie_dst = (l == 1) ? (out + (size_t)NU * HD) : xm;
        float* user_dst  = (l == 1) ? out : xu;
        finalize_k<<<(NM * HD + 255) / 256, 256>>>(accm, bias + (size_t)p0 * 64, movie_dst, NM * HD);
        finalize_k<<<(NU * HD + 255) / 256, 256>>>(accu, bias + (size_t)p1 * 64, user_dst,  NU * HD);

        cu = xu;
        cm = xm;
    }
}

// round 2
// speedup vs baseline: 1.4926x; 1.4926x over previous
#include <cuda_runtime.h>
#include <cuda_bf16.h>
#include <cstdint>

// Problem constants (fixed by the dataset)
#define NU 100000          // users
#define NM 20000           // movies
#define NE 1000000         // edges per direction
#define NLOOP 20000        // min(NU,NM) self loops
#define ET (NE + NLOOP)    // total edges per conv
#define HD 64              // hidden dim

// ---------------- scratch (static device globals) ---------------------------
__device__ float g_xl[(size_t)NU * HD];      // src projection (max size)
__device__ float g_xr[(size_t)NU * HD];      // dst projection (max size)
__device__ float g_s[NU];                    // segment sum of exp(score)
__device__ float g_accu[(size_t)NU * HD];    // user-dst accumulator
__device__ float g_accm[(size_t)NM * HD];    // movie-dst accumulator
__device__ float g_xu[(size_t)NU * HD];      // layer-0 user output
__device__ float g_xm[(size_t)NM * HD];      // layer-0 movie output

// ---------------- GEMM: Y[N,64] = X[N,64] @ W[64,64] + B[64] ----------------
__global__ void gemm_bias_k(const float* __restrict__ X, const float* __restrict__ W,
                            const float* __restrict__ B, float* __restrict__ Y, int N)
{
    __shared__ float Xs[64][65];
    __shared__ float Ws[64][64];
    int tid  = threadIdx.x;              // 256 threads
    int row0 = blockIdx.x * 64;

    const float4* W4 = (const float4*)W;
    float4* Ws4 = (float4*)Ws;
#pragma unroll
    for (int i = 0; i < 4; i++) Ws4[tid + i * 256] = W4[tid + i * 256];

#pragma unroll
    for (int i = 0; i < 4; i++) {
        int idx = tid + i * 256;         // float4 index over [64][16]
        int r = idx >> 4, c4 = idx & 15;
        float4 v = make_float4(0.f, 0.f, 0.f, 0.f);
        if (row0 + r < N) v = ((const float4*)X)[(size_t)(row0 + r) * 16 + c4];
        Xs[r][c4 * 4 + 0] = v.x; Xs[r][c4 * 4 + 1] = v.y;
        Xs[r][c4 * 4 + 2] = v.z; Xs[r][c4 * 4 + 3] = v.w;
    }
    __syncthreads();

    int ty = tid >> 4, tx = tid & 15;    // 4 rows x 4 cols per thread
    float acc[4][4];
#pragma unroll
    for (int i = 0; i < 4; i++)
#pragma unroll
        for (int j = 0; j < 4; j++) acc[i][j] = 0.f;

#pragma unroll
    for (int k = 0; k < 64; k++) {
        float4 wv = ((const float4*)Ws)[k * 16 + tx];
        float x0 = Xs[ty * 4 + 0][k];
        float x1 = Xs[ty * 4 + 1][k];
        float x2 = Xs[ty * 4 + 2][k];
        float x3 = Xs[ty * 4 + 3][k];
        acc[0][0] += x0 * wv.x; acc[0][1] += x0 * wv.y; acc[0][2] += x0 * wv.z; acc[0][3] += x0 * wv.w;
        acc[1][0] += x1 * wv.x; acc[1][1] += x1 * wv.y; acc[1][2] += x1 * wv.z; acc[1][3] += x1 * wv.w;
        acc[2][0] += x2 * wv.x; acc[2][1] += x2 * wv.y; acc[2][2] += x2 * wv.z; acc[2][3] += x2 * wv.w;
        acc[3][0] += x3 * wv.x; acc[3][1] += x3 * wv.y; acc[3][2] += x3 * wv.z; acc[3][3] += x3 * wv.w;
    }

    float4 bv = ((const float4*)B)[tx];
#pragma unroll
    for (int i = 0; i < 4; i++) {
        int r = row0 + ty * 4 + i;
        if (r < N) {
            float4 o;
            o.x = acc[i][0] + bv.x; o.y = acc[i][1] + bv.y;
            o.z = acc[i][2] + bv.z; o.w = acc[i][3] + bv.w;
            ((float4*)Y)[(size_t)r * 16 + tx] = o;
        }
    }
}

// ---------------- per-conv init: zero acc + segment sums --------------------
__global__ void init_k(float* __restrict__ sbuf, float* __restrict__ acc, int ndst)
{
    int i = blockIdx.x * blockDim.x + threadIdx.x;
    int n4 = ndst * (HD / 4);
    if (i < n4) ((float4*)acc)[i] = make_float4(0.f, 0.f, 0.f, 0.f);
    if (i < ndst) sbuf[i] = 0.f;
}

// ---------------- fused edge pass: score -> exp -> sum -> scatter -----------
// out[d] = sum_e exp(score_e) * xl[src_e]   (normalized by s[d] in finalize)
__global__ void edge_fused_k(const int* __restrict__ esrc, const int* __restrict__ edst,
                             const float* __restrict__ xl, const float* __restrict__ xr,
                             const float* __restrict__ att,
                             float* __restrict__ sbuf, float* __restrict__ acc)
{
    int t = blockIdx.x * blockDim.x + threadIdx.x;
    int g = t >> 4;
    if (g >= ET) return;
    int lane = t & 15;
    int s, d;
    if (g < NE) { s = esrc[g]; d = edst[g]; } else { s = g - NE; d = s; }

    float4 a = ((const float4*)xl)[(size_t)s * 16 + lane];
    float4 b = ((const float4*)xr)[(size_t)d * 16 + lane];
    float4 w = ((const float4*)att)[lane];

    float vx = a.x + b.x; vx = vx > 0.f ? vx : 0.2f * vx;
    float vy = a.y + b.y; vy = vy > 0.f ? vy : 0.2f * vy;
    float vz = a.z + b.z; vz = vz > 0.f ? vz : 0.2f * vz;
    float vw = a.w + b.w; vw = vw > 0.f ? vw : 0.2f * vw;
    float p = vx * w.x + vy * w.y + vz * w.z + vw * w.w;
#pragma unroll
    for (int o = 8; o > 0; o >>= 1) p += __shfl_xor_sync(0xffffffffu, p, o);
    // all 16 lanes of the group now hold the full dot product
    float ex = __expf(p);

    if (lane == 0) atomicAdd(&sbuf[d], ex);

    a.x *= ex; a.y *= ex; a.z *= ex; a.w *= ex;
    float* pp = acc + (size_t)d * HD + lane * 4;
    asm volatile("red.global.add.v4.f32 [%0], {%1,%2,%3,%4};"
                 :: "l"(pp), "f"(a.x), "f"(a.y), "f"(a.z), "f"(a.w) : "memory");
}

// ---------------- finalize: /segsum, + bias, SELU ---------------------------
__global__ void finalize_k(const float* __restrict__ acc, const float* __restrict__ sbuf,
                           const float* __restrict__ bias, float* __restrict__ out, int n)
{
    int i = blockIdx.x * blockDim.x + threadIdx.x;
    if (i >= n) return;
    float inv = 1.f / (sbuf[i >> 6] + 1e-16f);
    float x = acc[i] * inv + bias[i & 63];
    const float SCALE = 1.0507009873554805f;
    const float SA    = 1.7580993408473766f;   // scale * alpha
    out[i] = x > 0.f ? SCALE * x : SA * (__expf(x) - 1.f);
}

// ---------------- host-side conv driver -------------------------------------
static void launch_conv(const float* xs, int ns, const float* xd, int nd,
                        const int* edge,
                        const float* Wl_, const float* bl_,
                        const float* Wr_, const float* br_, const float* att_,
                        float* xl, float* xr, float* sb, float* acc)
{
    gemm_bias_k<<<(ns + 63) / 64, 256>>>(xs, Wl_, bl_, xl, ns);
    gemm_bias_k<<<(nd + 63) / 64, 256>>>(xd, Wr_, br_, xr, nd);
    init_k<<<(nd * (HD / 4) + 255) / 256, 256>>>(sb, acc, nd);
    edge_fused_k<<<((long)ET * 16 + 255) / 256, 256>>>(edge, edge + NE, xl, xr, att_, sb, acc);
}

extern "C" void kernel_launch(void* const* d_in, const int* in_sizes, int n_in,
                              void* d_out, int out_size)
{
    const float* x_user  = (const float*)d_in[0];
    const float* x_movie = (const float*)d_in[1];
    const int*   e_u2m   = (const int*)d_in[2];
    const int*   e_m2u   = (const int*)d_in[3];
    const float* Wl      = (const float*)d_in[4];
    const float* bl      = (const float*)d_in[5];
    const float* Wr      = (const float*)d_in[6];
    const float* br      = (const float*)d_in[7];
    const float* att     = (const float*)d_in[8];
    const float* bias    = (const float*)d_in[9];
    float* out = (float*)d_out;

    float *xl, *xr, *sb, *accu, *accm, *xu, *xm;
    cudaGetSymbolAddress((void**)&xl,   g_xl);
    cudaGetSymbolAddress((void**)&xr,   g_xr);
    cudaGetSymbolAddress((void**)&sb,   g_s);
    cudaGetSymbolAddress((void**)&accu, g_accu);
    cudaGetSymbolAddress((void**)&accm, g_accm);
    cudaGetSymbolAddress((void**)&xu,   g_xu);
    cudaGetSymbolAddress((void**)&xm,   g_xm);

    const float* cu = x_user;
    const float* cm = x_movie;

    for (int l = 0; l < 2; l++) {
        int p0 = l * 2 + 0;   // user -> movie
        int p1 = l * 2 + 1;   // movie -> user

        // conv u2m: src=user, dst=movie  -> accm
        launch_conv(cu, NU, cm, NM, e_u2m,
                    Wl + (size_t)p0 * 4096, bl + (size_t)p0 * 64,
                    Wr + (size_t)p0 * 4096, br + (size_t)p0 * 64,
                    att + (size_t)p0 * 64,
                    xl, xr, sb, accm);

        float* sbu = sb;  // reuse after movie conv's finalize ordering below
        // conv m2u: src=movie, dst=user  -> accu (reads OLD features)
        // NOTE: needs its own segment-sum buffer since movie conv's sb is
        // consumed by finalize AFTER this launch — so split sb usage:
        // movie uses sb[0:NM], user uses a disjoint region? g_s is NU long;
        // movie conv wrote sb[0:NM]. Finalize for movie reads sb before user
        // conv would overwrite. Order: run movie finalize between convs.
        finalize_k<<<(NM * HD + 255) / 256, 256>>>(accm, sb, bias + (size_t)p0 * 64,
                                                   (l == 1) ? (out + (size_t)NU * HD) : xm, NM * HD);

        launch_conv(cm, NM, cu, NU, e_m2u,
                    Wl + (size_t)p1 * 4096, bl + (size_t)p1 * 64,
                    Wr + (size_t)p1 * 4096, br + (size_t)p1 * 64,
                    att + (size_t)p1 * 64,
                    xl, xr, sbu, accu);

        finalize_k<<<(NU * HD + 255) / 256, 256>>>(accu, sb, bias + (size_t)p1 * 64,
                                                   (l == 1) ? out : xu, NU * HD);

        cu = xu;
        cm = xm;
    }
}